// round 5
// baseline (speedup 1.0000x reference)
#include <cuda_runtime.h>

// Problem constants
#define NB    2
#define NT    5
#define NGRID 1024            // 32*32 spatial points
#define NQ    5120            // NT * NGRID

// Diagonal-block band values: [b*5+ti][row][25 offsets, padded to 32]
__device__ float g_diag[NB * NT * NGRID * 32];
// Off-diagonal-block band values: [b*4+i][row][9 offsets, padded to 16]
__device__ float g_off[NB * 4 * NGRID * 16];

__device__ __forceinline__ float sp10(float x) {
    float z = 10.f * x;
    return (fmaxf(z, 0.f) + log1pf(expf(-fabsf(z)))) * 0.1f;
}

// Decode the 9 stencil coefficients of operator (b, i) at point p.
__device__ __forceinline__ void decode_point(const float* __restrict__ params,
                                             int b, int i, int p, float co[9]) {
    int t = i + 1;
    // kappa / m use the "raw reshape" mixing: flat = p*5 + t over a (5,32,32) block
    int flat = p * 5 + t;
    int tor  = flat >> 10;
    int rem  = flat & 1023;

    const float* Pb = params + b * 35 * NGRID;
    float kap = sp10(Pb[(0  + tor) * NGRID + rem]);
    float m1  =      Pb[(5  + tor) * NGRID + rem];
    float m2  =      Pb[(10 + tor) * NGRID + rem];

    float gam = sp10(Pb[(15 + t) * NGRID + p]);
    float vx  =      Pb[(20 + t) * NGRID + p];
    float vy  =      Pb[(25 + t) * NGRID + p];

    float H11 = gam + vx * vx;
    float H22 = gam + vy * vy;
    float H12 = vx * vy;

    int y = p >> 5, x = p & 31;

    co[4] = kap * kap + 2.f * H11 + 2.f * H22;
    co[5] = (x + 1 < 32)            ? (-H11 + 0.5f * m1) : 0.f;
    co[3] = (x - 1 >= 0)            ? (-H11 - 0.5f * m1) : 0.f;
    co[7] = (y + 1 < 32)            ? (-H22 + 0.5f * m2) : 0.f;
    co[1] = (y - 1 >= 0)            ? (-H22 - 0.5f * m2) : 0.f;
    co[8] = (x + 1 < 32 && y + 1 < 32) ? (-0.5f * H12) : 0.f;
    co[0] = (x - 1 >= 0 && y - 1 >= 0) ? (-0.5f * H12) : 0.f;
    co[2] = (x + 1 < 32 && y - 1 >= 0) ? ( 0.5f * H12) : 0.f;
    co[6] = (x - 1 >= 0 && y + 1 < 32) ? ( 0.5f * H12) : 0.f;
}

// ---------------------------------------------------------------------------
// Fused decode+band kernel, 224 blocks, halo-only decode.
//   blocks [0,160):   diag. bx = bt*16 + sub (sub 0..15); bt = b*5+ti;
//                     rows [sub*64, +64); decode y in [2*sub-2, 2*sub+4), 192 pts
//   blocks [160,224): off.  idx = bx-160 = bi*8 + sub (sub 0..7);
//                     rows [sub*128, +128); decode y in [4*sub-1, 4*sub+5), 192 pts
// smem sco[o][lp] with lp = p - base_y*32.
// ---------------------------------------------------------------------------
#define SPAN_MAX 192

__global__ void __launch_bounds__(256) precompute_kernel(const float* __restrict__ params) {
    __shared__ float sco[9 * SPAN_MAX];   // 6.75 KB

    int bx  = blockIdx.x;
    int tid = threadIdx.x;

    bool is_diag = bx < 160;
    int b, i, ti = 0, sub, base_y, span;
    if (is_diag) {
        sub = bx & 15;
        int bt = bx >> 4;          // 0..9
        ti = bt % 5;
        b  = bt / 5;
        i  = (ti == 0) ? 0 : ti - 1;
        base_y = 2 * sub - 2; span = 6;
    } else {
        int idx = bx - 160;
        sub = idx & 7;
        int bi = idx >> 3;         // 0..7
        b = bi >> 2;
        i = bi & 3;
        base_y = 4 * sub - 1; span = 6;
    }

    int npts  = span << 5;
    int pbase = base_y << 5;       // lp = p - pbase
    for (int lp = tid; lp < npts; lp += 256) {
        int y = base_y + (lp >> 5);
        if (y >= 0 && y < 32) {
            float co[9];
            decode_point(params, b, i, (y << 5) + (lp & 31), co);
#pragma unroll
            for (int o = 0; o < 9; ++o)
                sco[o * SPAN_MAX + lp] = co[o];
        }
    }
    __syncthreads();

    if (is_diag) {
        int r0 = sub << 6;                       // 64 rows per block
        int rowbase = ((b * 5 + ti) << 10);
        for (int it = tid; it < 64 * 25; it += 256) {
            int lr  = it / 25;
            int o25 = it - lr * 25;
            int r   = r0 + lr;
            int dy  = o25 / 5 - 2, dx = o25 % 5 - 2;
            int ry = r >> 5, rx = r & 31;
            int cy = ry + dy, cx = rx + dx;
            float val = 0.f;
            if (cy >= 0 && cy < 32 && cx >= 0 && cx < 32) {
                int c = (cy << 5) + cx;
                int lc = c - pbase;
                int lrr = r - pbase;
                if (ti == 0) {
                    float acc = 0.f;
#pragma unroll
                    for (int dky = -1; dky <= 1; ++dky)
#pragma unroll
                    for (int dkx = -1; dkx <= 1; ++dkx) {
                        int ky = ry + dky, kx = rx + dkx;
                        int ody = cy - ky, odx = cx - kx;
                        if (ky >= 0 && ky < 32 && kx >= 0 && kx < 32 &&
                            ody >= -1 && ody <= 1 && odx >= -1 && odx <= 1) {
                            int lk = ((ky << 5) + kx) - pbase;
                            float a  = sco[((1 - dky) * 3 + (1 - dkx)) * SPAN_MAX + lk];
                            float bb = sco[((ody + 1) * 3 + (odx + 1)) * SPAN_MAX + lk];
                            acc = fmaf(a, bb, acc);
                        }
                    }
                    val = acc + ((o25 == 12) ? 1.05f : 0.f);
                } else {
                    float acc1 = 0.f, acc2 = 0.f;
#pragma unroll
                    for (int dky = -1; dky <= 1; ++dky)
#pragma unroll
                    for (int dkx = -1; dkx <= 1; ++dkx) {
                        int ky = ry + dky, kx = rx + dkx;
                        int ody = cy - ky, odx = cx - kx;
                        if (ky >= 0 && ky < 32 && kx >= 0 && kx < 32 &&
                            ody >= -1 && ody <= 1 && odx >= -1 && odx <= 1) {
                            int k  = (ky << 5) + kx;
                            int lk = k - pbase;
                            float dkr = (k == r) ? 1.f : 0.f;
                            float dkc = (k == c) ? 1.f : 0.f;
                            float iM_rk = sco[((dky + 1) * 3 + (dkx + 1)) * SPAN_MAX + lrr] + dkr;
                            float iM_kr = sco[((1 - dky) * 3 + (1 - dkx)) * SPAN_MAX + lk] + dkr;
                            float iM_kc = sco[((ody + 1) * 3 + (odx + 1)) * SPAN_MAX + lk] + dkc;
                            float iM_ck = sco[((1 - ody) * 3 + (1 - odx)) * SPAN_MAX + lc] + dkc;
                            acc1 = fmaf(iM_rk, iM_kc, acc1);
                            acc2 = fmaf(iM_ck, iM_kr, acc2);
                        }
                    }
                    val = 0.5f * (acc1 + acc2);
                    if (o25 == 12) val += (ti == 4) ? 0.05f : 1.05f;
                }
            }
            g_diag[(rowbase + r) * 32 + o25] = val;
        }
    } else {
        int r0 = sub << 7;                       // 128 rows per block
        int rowbase = ((b * 4 + i) << 10);
        for (int it = tid; it < 128 * 9; it += 256) {
            int lr = it / 9;
            int o9 = it - lr * 9;
            int r  = r0 + lr;
            int dy = o9 / 3 - 1, dx = o9 % 3 - 1;
            int ry = r >> 5, rx = r & 31;
            int cy = ry + dy, cx = rx + dx;
            float val = 0.f;
            if (cy >= 0 && cy < 32 && cx >= 0 && cx < 32) {
                int lc = ((cy << 5) + cx) - pbase;
                int lrr = r - pbase;
                float a  = sco[o9       * SPAN_MAX + lrr];   // A[r][c]
                float bb = sco[(8 - o9) * SPAN_MAX + lc];    // A[c][r]
                float dg = (o9 == 4) ? 2.f : 0.f;
                val = -0.5f * (a + bb + dg);
            }
            g_off[(rowbase + r) * 16 + o9] = val;
        }
    }
}

// ---------------------------------------------------------------------------
// Kernel 2: stream out Q. One block per global row. dy is scalar per thread.
// Plain write-back stores: dirty lines linger in L2 and drain after the
// timed window instead of forcing DRAM writes inside it.
// ---------------------------------------------------------------------------
__global__ void __launch_bounds__(256) write_q(float4* __restrict__ out) {
    int row = blockIdx.x;                 // 0..10239
    int b   = row >= NQ;
    int R   = row - (b ? NQ : 0);
    int ti  = R >> 10;
    int r   = R & 1023;

    int tid = threadIdx.x;
    int c0  = tid << 2;
    int ry  = r >> 5, rx = r & 31;
    int dy  = (c0 >> 5) - ry;             // uniform over the thread's 4 columns

    float4 z  = make_float4(0.f, 0.f, 0.f, 0.f);
    float4 d4 = z, lo4 = z, hi4 = z;

    if (dy >= -2 && dy <= 2) {
        int dxb = (c0 & 31) - rx;         // dx for j=0; j adds 0..3
        const float* drow = g_diag + ((((b * 5 + ti) << 10) + r) << 5)
                          + (dy + 2) * 5 + 2;
        float vd[4];
#pragma unroll
        for (int j = 0; j < 4; ++j) {
            int dx = dxb + j;
            vd[j] = (dx >= -2 && dx <= 2) ? drow[dx] : 0.f;
        }
        d4 = make_float4(vd[0], vd[1], vd[2], vd[3]);

        if (dy >= -1 && dy <= 1) {
            bool has_lo = (ti > 0), has_hi = (ti < 4);
            const float* lorow = g_off + ((((b * 4 + (ti - 1)) << 10) + r) << 4)
                               + (dy + 1) * 3 + 1;
            const float* hirow = g_off + ((((b * 4 + ti) << 10) + r) << 4)
                               + (dy + 1) * 3 + 1;
            float vl[4], vh[4];
#pragma unroll
            for (int j = 0; j < 4; ++j) {
                int dx = dxb + j;
                bool in1 = (dx >= -1 && dx <= 1);
                vl[j] = (in1 && has_lo) ? lorow[dx] : 0.f;
                vh[j] = (in1 && has_hi) ? hirow[dx] : 0.f;
            }
            lo4 = make_float4(vl[0], vl[1], vl[2], vl[3]);
            hi4 = make_float4(vh[0], vh[1], vh[2], vh[3]);
        }
    }

    float4* base = out + (long)row * 1280 + tid;
#pragma unroll
    for (int tj = 0; tj < 5; ++tj) {
        float4 v = z;
        if (tj == ti)          v = d4;
        else if (tj == ti - 1) v = lo4;
        else if (tj == ti + 1) v = hi4;
        base[tj * 256] = v;
    }
}

extern "C" void kernel_launch(void* const* d_in, const int* in_sizes, int n_in,
                              void* d_out, int out_size) {
    const float* params = (const float*)d_in[0];
    float4* out = (float4*)d_out;

    precompute_kernel<<<224, 256>>>(params);
    write_q<<<NB * NQ, 256>>>(out);
}

// round 6
// speedup vs baseline: 1.1519x; 1.1519x over previous
#include <cuda_runtime.h>

// Problem constants
#define NB    2
#define NT    5
#define NGRID 1024            // 32*32 spatial points
#define NQ    5120            // NT * NGRID

__device__ __forceinline__ float sp10(float x) {
    float z = 10.f * x;
    return (fmaxf(z, 0.f) + log1pf(expf(-fabsf(z)))) * 0.1f;
}

// Decode the 9 stencil coefficients of operator (b, i) at point p.
__device__ __forceinline__ void decode_point(const float* __restrict__ params,
                                             int b, int i, int p, float co[9]) {
    int t = i + 1;
    // kappa / m use the "raw reshape" mixing: flat = p*5 + t over a (5,32,32) block
    int flat = p * 5 + t;
    int tor  = flat >> 10;
    int rem  = flat & 1023;

    const float* Pb = params + b * 35 * NGRID;
    float kap = sp10(Pb[(0  + tor) * NGRID + rem]);
    float m1  =      Pb[(5  + tor) * NGRID + rem];
    float m2  =      Pb[(10 + tor) * NGRID + rem];

    float gam = sp10(Pb[(15 + t) * NGRID + p]);
    float vx  =      Pb[(20 + t) * NGRID + p];
    float vy  =      Pb[(25 + t) * NGRID + p];

    float H11 = gam + vx * vx;
    float H22 = gam + vy * vy;
    float H12 = vx * vy;

    int y = p >> 5, x = p & 31;

    co[4] = kap * kap + 2.f * H11 + 2.f * H22;
    co[5] = (x + 1 < 32)            ? (-H11 + 0.5f * m1) : 0.f;
    co[3] = (x - 1 >= 0)            ? (-H11 - 0.5f * m1) : 0.f;
    co[7] = (y + 1 < 32)            ? (-H22 + 0.5f * m2) : 0.f;
    co[1] = (y - 1 >= 0)            ? (-H22 - 0.5f * m2) : 0.f;
    co[8] = (x + 1 < 32 && y + 1 < 32) ? (-0.5f * H12) : 0.f;
    co[0] = (x - 1 >= 0 && y - 1 >= 0) ? (-0.5f * H12) : 0.f;
    co[2] = (x + 1 < 32 && y - 1 >= 0) ? ( 0.5f * H12) : 0.f;
    co[6] = (x - 1 >= 0 && y + 1 < 32) ? ( 0.5f * H12) : 0.f;
}

// ---------------------------------------------------------------------------
// Single fused kernel. One block per global Q row.
//  Phase 1: 50 threads decode the 5x5 neighborhood of r for the two relevant
//           operators (slot 0 = op max(ti-1,0), slot 1 = op min(ti,3)) -> smem.
//  Phase 2: 43 threads compute this row's band values (25 diag, 9 off-lo,
//           9 off-hi) -> smem.
//  Phase 3: all 256 threads write the row's 5 x 1024 floats (5 float4 each).
// ---------------------------------------------------------------------------
__global__ void __launch_bounds__(256) q_kernel(const float* __restrict__ params,
                                                float4* __restrict__ out) {
    __shared__ float sco[2][9][28];    // [slot][offset o][local 5x5 point]
    __shared__ float sdiag[28];
    __shared__ float slo[12];
    __shared__ float shi[12];

    int row = blockIdx.x;                 // 0..10239
    int b   = row >= NQ;
    int R   = row - (b ? NQ : 0);
    int ti  = R >> 10;
    int r   = R & 1023;
    int ry  = r >> 5, rx = r & 31;
    int tid = threadIdx.x;

    int iA = (ti == 0) ? 0 : ti - 1;      // diag + off-lo operator
    int iB = (ti < 4) ? ti : 3;           // off-hi operator

    // Phase 1: decode 2 x 25 neighborhood points.
    if (tid < 50) {
        int slot = tid >= 25;
        int l    = slot ? tid - 25 : tid;     // local 5x5 index
        int dy = l / 5 - 2, dx = l % 5 - 2;
        int y = ry + dy, x = rx + dx;
        float co[9] = {0.f, 0.f, 0.f, 0.f, 0.f, 0.f, 0.f, 0.f, 0.f};
        if (y >= 0 && y < 32 && x >= 0 && x < 32)
            decode_point(params, b, slot ? iB : iA, (y << 5) + x, co);
#pragma unroll
        for (int o = 0; o < 9; ++o)
            sco[slot][o][l] = co[o];
    }
    __syncthreads();

    // Phase 2: band values for this row.
    if (tid < 25) {
        int o25 = tid;
        int dy = o25 / 5 - 2, dx = o25 % 5 - 2;
        int cy = ry + dy, cx = rx + dx;
        float val = 0.f;
        if (cy >= 0 && cy < 32 && cx >= 0 && cx < 32) {
            if (ti == 0) {
                float acc = 0.f;
#pragma unroll
                for (int dky = -1; dky <= 1; ++dky)
#pragma unroll
                for (int dkx = -1; dkx <= 1; ++dkx) {
                    int ky = ry + dky, kx = rx + dkx;
                    int ody = cy - ky, odx = cx - kx;
                    if (ky >= 0 && ky < 32 && kx >= 0 && kx < 32 &&
                        ody >= -1 && ody <= 1 && odx >= -1 && odx <= 1) {
                        int lk = (dky + 2) * 5 + (dkx + 2);
                        float a  = sco[0][(1 - dky) * 3 + (1 - dkx)][lk];
                        float bb = sco[0][(ody + 1) * 3 + (odx + 1)][lk];
                        acc = fmaf(a, bb, acc);
                    }
                }
                val = acc + ((o25 == 12) ? 1.05f : 0.f);
            } else {
                int c = (cy << 5) + cx;
                float acc1 = 0.f, acc2 = 0.f;
#pragma unroll
                for (int dky = -1; dky <= 1; ++dky)
#pragma unroll
                for (int dkx = -1; dkx <= 1; ++dkx) {
                    int ky = ry + dky, kx = rx + dkx;
                    int ody = cy - ky, odx = cx - kx;
                    if (ky >= 0 && ky < 32 && kx >= 0 && kx < 32 &&
                        ody >= -1 && ody <= 1 && odx >= -1 && odx <= 1) {
                        int k  = (ky << 5) + kx;
                        int lk = (dky + 2) * 5 + (dkx + 2);
                        float dkr = (k == r) ? 1.f : 0.f;
                        float dkc = (k == c) ? 1.f : 0.f;
                        float iM_rk = sco[0][(dky + 1) * 3 + (dkx + 1)][12] + dkr;
                        float iM_kr = sco[0][(1 - dky) * 3 + (1 - dkx)][lk] + dkr;
                        float iM_kc = sco[0][(ody + 1) * 3 + (odx + 1)][lk] + dkc;
                        float iM_ck = sco[0][(1 - ody) * 3 + (1 - odx)][o25] + dkc;
                        acc1 = fmaf(iM_rk, iM_kc, acc1);
                        acc2 = fmaf(iM_ck, iM_kr, acc2);
                    }
                }
                val = 0.5f * (acc1 + acc2);
                if (o25 == 12) val += (ti == 4) ? 0.05f : 1.05f;
            }
        }
        sdiag[o25] = val;
    } else if (tid >= 32 && tid < 41) {
        // off-lo: -0.5*(A_{ti-1}[r][c] + A_{ti-1}[c][r] + 2*delta), slot 0
        int o9 = tid - 32;
        int dy = o9 / 3 - 1, dx = o9 % 3 - 1;
        int cy = ry + dy, cx = rx + dx;
        float val = 0.f;
        if (cy >= 0 && cy < 32 && cx >= 0 && cx < 32) {
            int lc = (dy + 2) * 5 + (dx + 2);
            float a  = sco[0][o9][12];
            float bb = sco[0][8 - o9][lc];
            val = -0.5f * (a + bb + ((o9 == 4) ? 2.f : 0.f));
        }
        slo[o9] = val;
    } else if (tid >= 64 && tid < 73) {
        // off-hi: operator ti, slot 1
        int o9 = tid - 64;
        int dy = o9 / 3 - 1, dx = o9 % 3 - 1;
        int cy = ry + dy, cx = rx + dx;
        float val = 0.f;
        if (cy >= 0 && cy < 32 && cx >= 0 && cx < 32) {
            int lc = (dy + 2) * 5 + (dx + 2);
            float a  = sco[1][o9][12];
            float bb = sco[1][8 - o9][lc];
            val = -0.5f * (a + bb + ((o9 == 4) ? 2.f : 0.f));
        }
        shi[o9] = val;
    }
    __syncthreads();

    // Phase 3: stream the row out. dy is scalar per thread (4 cols share a y-row).
    int c0 = tid << 2;
    int dy = (c0 >> 5) - ry;

    float4 z  = make_float4(0.f, 0.f, 0.f, 0.f);
    float4 d4 = z, lo4 = z, hi4 = z;

    if (dy >= -2 && dy <= 2) {
        int dxb = (c0 & 31) - rx;
        const float* drow = &sdiag[(dy + 2) * 5 + 2];
        float vd[4];
#pragma unroll
        for (int j = 0; j < 4; ++j) {
            int dx = dxb + j;
            vd[j] = (dx >= -2 && dx <= 2) ? drow[dx] : 0.f;
        }
        d4 = make_float4(vd[0], vd[1], vd[2], vd[3]);

        if (dy >= -1 && dy <= 1) {
            bool has_lo = (ti > 0), has_hi = (ti < 4);
            const float* lorow = &slo[(dy + 1) * 3 + 1];
            const float* hirow = &shi[(dy + 1) * 3 + 1];
            float vl[4], vh[4];
#pragma unroll
            for (int j = 0; j < 4; ++j) {
                int dx = dxb + j;
                bool in1 = (dx >= -1 && dx <= 1);
                vl[j] = (in1 && has_lo) ? lorow[dx] : 0.f;
                vh[j] = (in1 && has_hi) ? hirow[dx] : 0.f;
            }
            lo4 = make_float4(vl[0], vl[1], vl[2], vl[3]);
            hi4 = make_float4(vh[0], vh[1], vh[2], vh[3]);
        }
    }

    float4* base = out + (long)row * 1280 + tid;
#pragma unroll
    for (int tj = 0; tj < 5; ++tj) {
        float4 v = z;
        if (tj == ti)          v = d4;
        else if (tj == ti - 1) v = lo4;
        else if (tj == ti + 1) v = hi4;
        base[tj * 256] = v;
    }
}

extern "C" void kernel_launch(void* const* d_in, const int* in_sizes, int n_in,
                              void* d_out, int out_size) {
    const float* params = (const float*)d_in[0];
    float4* out = (float4*)d_out;

    q_kernel<<<NB * NQ, 256>>>(params, out);
}

// round 7
// speedup vs baseline: 1.2493x; 1.0846x over previous
#include <cuda_runtime.h>

// Problem constants
#define NB    2
#define NT    5
#define NGRID 1024            // 32*32 spatial points
#define NQ    5120            // NT * NGRID

__device__ __forceinline__ float sp10(float x) {
    float z = 10.f * x;
    return (fmaxf(z, 0.f) + log1pf(expf(-fabsf(z)))) * 0.1f;
}

// Decode the 9 stencil coefficients of operator (b, i) at point p.
__device__ __forceinline__ void decode_point(const float* __restrict__ params,
                                             int b, int i, int p, float co[9]) {
    int t = i + 1;
    // kappa / m use the "raw reshape" mixing: flat = p*5 + t over a (5,32,32) block
    int flat = p * 5 + t;
    int tor  = flat >> 10;
    int rem  = flat & 1023;

    const float* Pb = params + b * 35 * NGRID;
    float kap = sp10(Pb[(0  + tor) * NGRID + rem]);
    float m1  =      Pb[(5  + tor) * NGRID + rem];
    float m2  =      Pb[(10 + tor) * NGRID + rem];

    float gam = sp10(Pb[(15 + t) * NGRID + p]);
    float vx  =      Pb[(20 + t) * NGRID + p];
    float vy  =      Pb[(25 + t) * NGRID + p];

    float H11 = gam + vx * vx;
    float H22 = gam + vy * vy;
    float H12 = vx * vy;

    int y = p >> 5, x = p & 31;

    co[4] = kap * kap + 2.f * H11 + 2.f * H22;
    co[5] = (x + 1 < 32)            ? (-H11 + 0.5f * m1) : 0.f;
    co[3] = (x - 1 >= 0)            ? (-H11 - 0.5f * m1) : 0.f;
    co[7] = (y + 1 < 32)            ? (-H22 + 0.5f * m2) : 0.f;
    co[1] = (y - 1 >= 0)            ? (-H22 - 0.5f * m2) : 0.f;
    co[8] = (x + 1 < 32 && y + 1 < 32) ? (-0.5f * H12) : 0.f;
    co[0] = (x - 1 >= 0 && y - 1 >= 0) ? (-0.5f * H12) : 0.f;
    co[2] = (x + 1 < 32 && y - 1 >= 0) ? ( 0.5f * H12) : 0.f;
    co[6] = (x - 1 >= 0 && y + 1 < 32) ? ( 0.5f * H12) : 0.f;
}

// ---------------------------------------------------------------------------
// Single fused kernel, 4 consecutive global rows per block (2560 blocks).
// Rows r0..r0+3 share (b, ti, ry); decode window is y in [ry-2,ry+2],
// x in [rxb-2, rxb+5]: 5x8 = 40 points per operator, 2 operators.
//  Phase 1: 80 threads decode -> sco[2][9][40]
//  Phase 2: 100 threads diag (4 rows x 25), 36 off-lo, 36 off-hi -> smem
//  Phase 3: all 256 threads write 4 rows x 5 tj (20 float4 stores each)
// ---------------------------------------------------------------------------
__global__ void __launch_bounds__(256) q_kernel(const float* __restrict__ params,
                                                float4* __restrict__ out) {
    __shared__ float sco[2][9][40];    // [slot][offset o][local 5x8 point]
    __shared__ float sdiag[4][28];
    __shared__ float slo[4][12];
    __shared__ float shi[4][12];

    int row0 = blockIdx.x << 2;           // 0..10236, step 4
    int b    = row0 >= NQ;
    int R0   = row0 - (b ? NQ : 0);
    int ti   = R0 >> 10;
    int r0   = R0 & 1023;
    int ry   = r0 >> 5;                   // same for all 4 rows (4 | 32)
    int rxb  = r0 & 31;                   // rx of row g is rxb + g
    int tid  = threadIdx.x;

    int iA = (ti == 0) ? 0 : ti - 1;      // diag + off-lo operator
    int iB = (ti < 4) ? ti : 3;           // off-hi operator

    // Phase 1: decode 2 x 40 window points.
    if (tid < 80) {
        int slot = tid >= 40;
        int l    = slot ? tid - 40 : tid;     // local 5x8 index
        int ly = l >> 3, lx = l & 7;
        int y = ry - 2 + ly, x = rxb - 2 + lx;
        float co[9] = {0.f, 0.f, 0.f, 0.f, 0.f, 0.f, 0.f, 0.f, 0.f};
        if (y >= 0 && y < 32 && x >= 0 && x < 32)
            decode_point(params, b, slot ? iB : iA, (y << 5) + x, co);
#pragma unroll
        for (int o = 0; o < 9; ++o)
            sco[slot][o][l] = co[o];
    }
    __syncthreads();

    // Phase 2: band values for the 4 rows.
    if (tid < 100) {
        int g   = tid / 25;
        int o25 = tid - g * 25;
        int rx  = rxb + g;
        int r   = (ry << 5) + rx;
        int dy = o25 / 5 - 2, dx = o25 % 5 - 2;
        int cy = ry + dy, cx = rx + dx;
        int lr = 18 + g;                        // r's local index: 2*8 + (g+2)
        float val = 0.f;
        if (cy >= 0 && cy < 32 && cx >= 0 && cx < 32) {
            int lc = (dy + 2) * 8 + (g + dx + 2);
            if (ti == 0) {
                float acc = 0.f;
#pragma unroll
                for (int dky = -1; dky <= 1; ++dky)
#pragma unroll
                for (int dkx = -1; dkx <= 1; ++dkx) {
                    int ky = ry + dky, kx = rx + dkx;
                    int ody = cy - ky, odx = cx - kx;
                    if (ky >= 0 && ky < 32 && kx >= 0 && kx < 32 &&
                        ody >= -1 && ody <= 1 && odx >= -1 && odx <= 1) {
                        int lk = (dky + 2) * 8 + (g + dkx + 2);
                        float a  = sco[0][(1 - dky) * 3 + (1 - dkx)][lk];
                        float bb = sco[0][(ody + 1) * 3 + (odx + 1)][lk];
                        acc = fmaf(a, bb, acc);
                    }
                }
                val = acc + ((o25 == 12) ? 1.05f : 0.f);
            } else {
                int c = (cy << 5) + cx;
                float acc1 = 0.f, acc2 = 0.f;
#pragma unroll
                for (int dky = -1; dky <= 1; ++dky)
#pragma unroll
                for (int dkx = -1; dkx <= 1; ++dkx) {
                    int ky = ry + dky, kx = rx + dkx;
                    int ody = cy - ky, odx = cx - kx;
                    if (ky >= 0 && ky < 32 && kx >= 0 && kx < 32 &&
                        ody >= -1 && ody <= 1 && odx >= -1 && odx <= 1) {
                        int k  = (ky << 5) + kx;
                        int lk = (dky + 2) * 8 + (g + dkx + 2);
                        float dkr = (k == r) ? 1.f : 0.f;
                        float dkc = (k == c) ? 1.f : 0.f;
                        float iM_rk = sco[0][(dky + 1) * 3 + (dkx + 1)][lr] + dkr;
                        float iM_kr = sco[0][(1 - dky) * 3 + (1 - dkx)][lk] + dkr;
                        float iM_kc = sco[0][(ody + 1) * 3 + (odx + 1)][lk] + dkc;
                        float iM_ck = sco[0][(1 - ody) * 3 + (1 - odx)][lc] + dkc;
                        acc1 = fmaf(iM_rk, iM_kc, acc1);
                        acc2 = fmaf(iM_ck, iM_kr, acc2);
                    }
                }
                val = 0.5f * (acc1 + acc2);
                if (o25 == 12) val += (ti == 4) ? 0.05f : 1.05f;
            }
        }
        sdiag[g][o25] = val;
    } else if (tid >= 128 && tid < 164) {
        // off-lo: -0.5*(A_{ti-1}[r][c] + A_{ti-1}[c][r] + 2*delta), slot 0
        int t2 = tid - 128;
        int g  = t2 / 9;
        int o9 = t2 - g * 9;
        int rx = rxb + g;
        int dy = o9 / 3 - 1, dx = o9 % 3 - 1;
        int cy = ry + dy, cx = rx + dx;
        float val = 0.f;
        if (cy >= 0 && cy < 32 && cx >= 0 && cx < 32) {
            int lc = (dy + 2) * 8 + (g + dx + 2);
            float a  = sco[0][o9][18 + g];
            float bb = sco[0][8 - o9][lc];
            val = -0.5f * (a + bb + ((o9 == 4) ? 2.f : 0.f));
        }
        slo[g][o9] = val;
    } else if (tid >= 192 && tid < 228) {
        // off-hi: operator ti, slot 1
        int t2 = tid - 192;
        int g  = t2 / 9;
        int o9 = t2 - g * 9;
        int rx = rxb + g;
        int dy = o9 / 3 - 1, dx = o9 % 3 - 1;
        int cy = ry + dy, cx = rx + dx;
        float val = 0.f;
        if (cy >= 0 && cy < 32 && cx >= 0 && cx < 32) {
            int lc = (dy + 2) * 8 + (g + dx + 2);
            float a  = sco[1][o9][18 + g];
            float bb = sco[1][8 - o9][lc];
            val = -0.5f * (a + bb + ((o9 == 4) ? 2.f : 0.f));
        }
        shi[g][o9] = val;
    }
    __syncthreads();

    // Phase 3: stream the 4 rows out. dy is scalar per thread and per row.
    int c0 = tid << 2;
    int dy = (c0 >> 5) - ry;
    bool in2y = (dy >= -2 && dy <= 2);
    bool in1y = (dy >= -1 && dy <= 1);
    bool has_lo = (ti > 0), has_hi = (ti < 4);
    float4 z = make_float4(0.f, 0.f, 0.f, 0.f);

    float4* base0 = out + (long)row0 * 1280 + tid;

#pragma unroll
    for (int g = 0; g < 4; ++g) {
        float4 d4 = z, lo4 = z, hi4 = z;
        if (in2y) {
            int dxb = (c0 & 31) - (rxb + g);
            const float* drow = &sdiag[g][(dy + 2) * 5 + 2];
            float vd[4];
#pragma unroll
            for (int j = 0; j < 4; ++j) {
                int dx = dxb + j;
                vd[j] = (dx >= -2 && dx <= 2) ? drow[dx] : 0.f;
            }
            d4 = make_float4(vd[0], vd[1], vd[2], vd[3]);

            if (in1y) {
                const float* lorow = &slo[g][(dy + 1) * 3 + 1];
                const float* hirow = &shi[g][(dy + 1) * 3 + 1];
                float vl[4], vh[4];
#pragma unroll
                for (int j = 0; j < 4; ++j) {
                    int dx = dxb + j;
                    bool in1 = (dx >= -1 && dx <= 1);
                    vl[j] = (in1 && has_lo) ? lorow[dx] : 0.f;
                    vh[j] = (in1 && has_hi) ? hirow[dx] : 0.f;
                }
                lo4 = make_float4(vl[0], vl[1], vl[2], vl[3]);
                hi4 = make_float4(vh[0], vh[1], vh[2], vh[3]);
            }
        }
        float4* base = base0 + g * 1280;
#pragma unroll
        for (int tj = 0; tj < 5; ++tj) {
            float4 v = z;
            if (tj == ti)          v = d4;
            else if (tj == ti - 1) v = lo4;
            else if (tj == ti + 1) v = hi4;
            base[tj * 256] = v;
        }
    }
}

extern "C" void kernel_launch(void* const* d_in, const int* in_sizes, int n_in,
                              void* d_out, int out_size) {
    const float* params = (const float*)d_in[0];
    float4* out = (float4*)d_out;

    q_kernel<<<(NB * NQ) / 4, 256>>>(params, out);
}

// round 8
// speedup vs baseline: 1.2516x; 1.0018x over previous
#include <cuda_runtime.h>

// Problem constants
#define NB    2
#define NT    5
#define NGRID 1024            // 32*32 spatial points
#define NQ    5120            // NT * NGRID

__device__ __forceinline__ float sp10(float x) {
    float z = 10.f * x;
    return (fmaxf(z, 0.f) + log1pf(expf(-fabsf(z)))) * 0.1f;
}

// Decode the 9 stencil coefficients of operator (b, i) at point p.
__device__ __forceinline__ void decode_point(const float* __restrict__ params,
                                             int b, int i, int p, float co[9]) {
    int t = i + 1;
    // kappa / m use the "raw reshape" mixing: flat = p*5 + t over a (5,32,32) block
    int flat = p * 5 + t;
    int tor  = flat >> 10;
    int rem  = flat & 1023;

    const float* Pb = params + b * 35 * NGRID;
    float kap = sp10(Pb[(0  + tor) * NGRID + rem]);
    float m1  =      Pb[(5  + tor) * NGRID + rem];
    float m2  =      Pb[(10 + tor) * NGRID + rem];

    float gam = sp10(Pb[(15 + t) * NGRID + p]);
    float vx  =      Pb[(20 + t) * NGRID + p];
    float vy  =      Pb[(25 + t) * NGRID + p];

    float H11 = gam + vx * vx;
    float H22 = gam + vy * vy;
    float H12 = vx * vy;

    int y = p >> 5, x = p & 31;

    co[4] = kap * kap + 2.f * H11 + 2.f * H22;
    co[5] = (x + 1 < 32)            ? (-H11 + 0.5f * m1) : 0.f;
    co[3] = (x - 1 >= 0)            ? (-H11 - 0.5f * m1) : 0.f;
    co[7] = (y + 1 < 32)            ? (-H22 + 0.5f * m2) : 0.f;
    co[1] = (y - 1 >= 0)            ? (-H22 - 0.5f * m2) : 0.f;
    co[8] = (x + 1 < 32 && y + 1 < 32) ? (-0.5f * H12) : 0.f;
    co[0] = (x - 1 >= 0 && y - 1 >= 0) ? (-0.5f * H12) : 0.f;
    co[2] = (x + 1 < 32 && y - 1 >= 0) ? ( 0.5f * H12) : 0.f;
    co[6] = (x - 1 >= 0 && y + 1 < 32) ? ( 0.5f * H12) : 0.f;
}

// ---------------------------------------------------------------------------
// Single fused kernel, 2 consecutive global rows per block (5120 blocks),
// forced to 8 blocks/SM (full 64-warp occupancy).
// Rows r0, r0+1 share (b, ti, ry); decode window is y in [ry-2,ry+2],
// x in [rxb-2, rxb+3]: 5x6 = 30 points per operator, 2 operators.
//  Phase 1: 60 threads decode -> sco[2][9][30]
//  Phase 2: 50 threads diag (2 rows x 25), 18 off-lo, 18 off-hi -> smem
//  Phase 3: all 256 threads write 2 rows x 5 tj (10 float4 stores each)
// ---------------------------------------------------------------------------
__global__ void __launch_bounds__(256, 8) q_kernel(const float* __restrict__ params,
                                                   float4* __restrict__ out) {
    __shared__ float sco[2][9][32];    // [slot][offset o][local 5x6 point]
    __shared__ float sdiag[2][28];
    __shared__ float slo[2][12];
    __shared__ float shi[2][12];

    int row0 = blockIdx.x << 1;           // 0..10238, step 2
    int b    = row0 >= NQ;
    int R0   = row0 - (b ? NQ : 0);
    int ti   = R0 >> 10;
    int r0   = R0 & 1023;
    int ry   = r0 >> 5;                   // same for both rows (2 | 32)
    int rxb  = r0 & 31;                   // rx of row g is rxb + g
    int tid  = threadIdx.x;

    int iA = (ti == 0) ? 0 : ti - 1;      // diag + off-lo operator
    int iB = (ti < 4) ? ti : 3;           // off-hi operator

    // Phase 1: decode 2 x 30 window points.
    if (tid < 60) {
        int slot = tid >= 30;
        int l    = slot ? tid - 30 : tid;     // local 5x6 index
        int ly = l / 6, lx = l - ly * 6;
        int y = ry - 2 + ly, x = rxb - 2 + lx;
        float co[9] = {0.f, 0.f, 0.f, 0.f, 0.f, 0.f, 0.f, 0.f, 0.f};
        if (y >= 0 && y < 32 && x >= 0 && x < 32)
            decode_point(params, b, slot ? iB : iA, (y << 5) + x, co);
#pragma unroll
        for (int o = 0; o < 9; ++o)
            sco[slot][o][l] = co[o];
    }
    __syncthreads();

    // Phase 2: band values for the 2 rows.
    if (tid < 50) {
        int g   = tid >= 25;
        int o25 = g ? tid - 25 : tid;
        int rx  = rxb + g;
        int r   = (ry << 5) + rx;
        int dy = o25 / 5 - 2, dx = o25 % 5 - 2;
        int cy = ry + dy, cx = rx + dx;
        int lr = 14 + g;                        // r's local index: 2*6 + (g+2)
        float val = 0.f;
        if (cy >= 0 && cy < 32 && cx >= 0 && cx < 32) {
            int lc = (dy + 2) * 6 + (g + dx + 2);
            if (ti == 0) {
                float acc = 0.f;
#pragma unroll
                for (int dky = -1; dky <= 1; ++dky)
#pragma unroll
                for (int dkx = -1; dkx <= 1; ++dkx) {
                    int ky = ry + dky, kx = rx + dkx;
                    int ody = cy - ky, odx = cx - kx;
                    if (ky >= 0 && ky < 32 && kx >= 0 && kx < 32 &&
                        ody >= -1 && ody <= 1 && odx >= -1 && odx <= 1) {
                        int lk = (dky + 2) * 6 + (g + dkx + 2);
                        float a  = sco[0][(1 - dky) * 3 + (1 - dkx)][lk];
                        float bb = sco[0][(ody + 1) * 3 + (odx + 1)][lk];
                        acc = fmaf(a, bb, acc);
                    }
                }
                val = acc + ((o25 == 12) ? 1.05f : 0.f);
            } else {
                int c = (cy << 5) + cx;
                float acc1 = 0.f, acc2 = 0.f;
#pragma unroll
                for (int dky = -1; dky <= 1; ++dky)
#pragma unroll
                for (int dkx = -1; dkx <= 1; ++dkx) {
                    int ky = ry + dky, kx = rx + dkx;
                    int ody = cy - ky, odx = cx - kx;
                    if (ky >= 0 && ky < 32 && kx >= 0 && kx < 32 &&
                        ody >= -1 && ody <= 1 && odx >= -1 && odx <= 1) {
                        int k  = (ky << 5) + kx;
                        int lk = (dky + 2) * 6 + (g + dkx + 2);
                        float dkr = (k == r) ? 1.f : 0.f;
                        float dkc = (k == c) ? 1.f : 0.f;
                        float iM_rk = sco[0][(dky + 1) * 3 + (dkx + 1)][lr] + dkr;
                        float iM_kr = sco[0][(1 - dky) * 3 + (1 - dkx)][lk] + dkr;
                        float iM_kc = sco[0][(ody + 1) * 3 + (odx + 1)][lk] + dkc;
                        float iM_ck = sco[0][(1 - ody) * 3 + (1 - odx)][lc] + dkc;
                        acc1 = fmaf(iM_rk, iM_kc, acc1);
                        acc2 = fmaf(iM_ck, iM_kr, acc2);
                    }
                }
                val = 0.5f * (acc1 + acc2);
                if (o25 == 12) val += (ti == 4) ? 0.05f : 1.05f;
            }
        }
        sdiag[g][o25] = val;
    } else if (tid >= 64 && tid < 82) {
        // off-lo: -0.5*(A_{ti-1}[r][c] + A_{ti-1}[c][r] + 2*delta), slot 0
        int t2 = tid - 64;
        int g  = t2 >= 9;
        int o9 = g ? t2 - 9 : t2;
        int rx = rxb + g;
        int dy = o9 / 3 - 1, dx = o9 % 3 - 1;
        int cy = ry + dy, cx = rx + dx;
        float val = 0.f;
        if (cy >= 0 && cy < 32 && cx >= 0 && cx < 32) {
            int lc = (dy + 2) * 6 + (g + dx + 2);
            float a  = sco[0][o9][14 + g];
            float bb = sco[0][8 - o9][lc];
            val = -0.5f * (a + bb + ((o9 == 4) ? 2.f : 0.f));
        }
        slo[g][o9] = val;
    } else if (tid >= 96 && tid < 114) {
        // off-hi: operator ti, slot 1
        int t2 = tid - 96;
        int g  = t2 >= 9;
        int o9 = g ? t2 - 9 : t2;
        int rx = rxb + g;
        int dy = o9 / 3 - 1, dx = o9 % 3 - 1;
        int cy = ry + dy, cx = rx + dx;
        float val = 0.f;
        if (cy >= 0 && cy < 32 && cx >= 0 && cx < 32) {
            int lc = (dy + 2) * 6 + (g + dx + 2);
            float a  = sco[1][o9][14 + g];
            float bb = sco[1][8 - o9][lc];
            val = -0.5f * (a + bb + ((o9 == 4) ? 2.f : 0.f));
        }
        shi[g][o9] = val;
    }
    __syncthreads();

    // Phase 3: stream the 2 rows out. dy is scalar per thread and per row.
    int c0 = tid << 2;
    int dy = (c0 >> 5) - ry;
    bool in2y = (dy >= -2 && dy <= 2);
    bool in1y = (dy >= -1 && dy <= 1);
    bool has_lo = (ti > 0), has_hi = (ti < 4);
    float4 z = make_float4(0.f, 0.f, 0.f, 0.f);

    float4* base0 = out + (long)row0 * 1280 + tid;

#pragma unroll
    for (int g = 0; g < 2; ++g) {
        float4 d4 = z, lo4 = z, hi4 = z;
        if (in2y) {
            int dxb = (c0 & 31) - (rxb + g);
            const float* drow = &sdiag[g][(dy + 2) * 5 + 2];
            float vd[4];
#pragma unroll
            for (int j = 0; j < 4; ++j) {
                int dx = dxb + j;
                vd[j] = (dx >= -2 && dx <= 2) ? drow[dx] : 0.f;
            }
            d4 = make_float4(vd[0], vd[1], vd[2], vd[3]);

            if (in1y) {
                const float* lorow = &slo[g][(dy + 1) * 3 + 1];
                const float* hirow = &shi[g][(dy + 1) * 3 + 1];
                float vl[4], vh[4];
#pragma unroll
                for (int j = 0; j < 4; ++j) {
                    int dx = dxb + j;
                    bool in1 = (dx >= -1 && dx <= 1);
                    vl[j] = (in1 && has_lo) ? lorow[dx] : 0.f;
                    vh[j] = (in1 && has_hi) ? hirow[dx] : 0.f;
                }
                lo4 = make_float4(vl[0], vl[1], vl[2], vl[3]);
                hi4 = make_float4(vh[0], vh[1], vh[2], vh[3]);
            }
        }
        float4* base = base0 + g * 1280;
#pragma unroll
        for (int tj = 0; tj < 5; ++tj) {
            float4 v = z;
            if (tj == ti)          v = d4;
            else if (tj == ti - 1) v = lo4;
            else if (tj == ti + 1) v = hi4;
            base[tj * 256] = v;
        }
    }
}

extern "C" void kernel_launch(void* const* d_in, const int* in_sizes, int n_in,
                              void* d_out, int out_size) {
    const float* params = (const float*)d_in[0];
    float4* out = (float4*)d_out;

    q_kernel<<<(NB * NQ) / 2, 256>>>(params, out);
}